// round 10
// baseline (speedup 1.0000x reference)
#include <cuda_runtime.h>
#include <stdint.h>

// ---------------------------------------------------------------------------
// AdaptiveUnpooling v10:
//   - serial single-stream spine (NO forks: overlapping bulk kernels with the
//     latency-bound edge kernel robs its occupancy — measured R7, R9).
//   - EXACT 32-bit quotient hash (16MB table): key = lo*N+hi < 2^34 permuted
//     by an invertible multiply mod 2^34; top 22 bits = slot, low 12 bits in
//     the stored value with probe displacement; bijective => exact dedup.
//   - adjacency array per target, slot = returning cnt atomicAdd.
//   - scatter kernel also writes g_pos (pos_kernel folded in).
//   - gather: 16 lanes/node, int4 adjacency loads, one non-atomic store.
// ---------------------------------------------------------------------------

#define TAB_BITS 22
#define TAB_SIZE (1u << TAB_BITS)      // 4M slots * 4B = 16MB (L2-resident)
#define MAX_N    131072
#define ADJ_DEG  96
#define UB       4
#define EDGE_BLOCKS  740               // 148 SMs * 5 blocks/SM
#define EDGE_THREADS 256

__device__ unsigned g_hash[TAB_SIZE];
__device__ int g_cnt[MAX_N];
__device__ int g_pos[MAX_N];
__device__ int g_adj[MAX_N * ADJ_DEG];

#define KEY_MASK ((1ULL << 34) - 1)
#define KEY_MUL  0x9E3779B97F4A7C15ULL   // odd => invertible mod 2^34

__global__ void clear_kernel(int N) {
    const int stride = gridDim.x * blockDim.x;
    const int tid = blockIdx.x * blockDim.x + threadIdx.x;
    uint4* h4 = reinterpret_cast<uint4*>(g_hash);
    for (unsigned i = tid; i < TAB_SIZE / 4; i += stride)
        h4[i] = make_uint4(0u, 0u, 0u, 0u);
    for (int i = tid; i < N; i += stride) { g_cnt[i] = 0; g_pos[i] = -1; }
}

// Copy present rows AND build pos map: thread c==0 of row r writes pos.
__global__ void scatter_kernel(const float4* __restrict__ x4,
                               const int* __restrict__ perm,
                               float4* __restrict__ out4,
                               int P, int Cv) {
    const int gtid = blockIdx.x * blockDim.x + threadIdx.x;
    const int r = gtid / Cv;
    const int c = gtid - r * Cv;
    if (r < P) {
        const int node = perm[r];
        if (c == 0) g_pos[node] = r;
        out4[(size_t)node * Cv + c] = x4[(size_t)r * Cv + c];
    }
}

// UB edges per batch per thread, phased for MLP; exact-wave grid-stride.
__global__ void __launch_bounds__(EDGE_THREADS, 5)
edge_kernel(const int* __restrict__ e0,
            const int* __restrict__ e1,
            int E, int N) {
    const int tid = blockIdx.x * blockDim.x + threadIdx.x;
    const int TOT = gridDim.x * blockDim.x;
    const int step = TOT * UB;

    for (int base = tid; base < E; base += step) {
        int a[UB], b[UB], pa[UB], pb[UB];
        bool act[UB];

        // Phase 1: coalesced edge loads
        #pragma unroll
        for (int k = 0; k < UB; k++) {
            const int j = base + k * TOT;
            const bool v = (j < E);
            act[k] = v;
            a[k] = v ? e0[j] : 0;
            b[k] = v ? e1[j] : 1;
        }

        // Phase 2: independent pos loads
        #pragma unroll
        for (int k = 0; k < UB; k++) {
            act[k] = act[k] && (a[k] != b[k]);
            pa[k] = act[k] ? g_pos[a[k]] : 0;
            pb[k] = act[k] ? g_pos[b[k]] : 0;
            act[k] = act[k] && ((pa[k] < 0) || (pb[k] < 0));
        }

        // Phase 3: quotient-hash slots + batched first-probe CAS (d = 0)
        unsigned h[UB], vbase[UB], old[UB];
        #pragma unroll
        for (int k = 0; k < UB; k++) {
            const unsigned lo = (unsigned)min(a[k], b[k]);
            const unsigned hi = (unsigned)max(a[k], b[k]);
            const uint64_t key = (uint64_t)lo * (uint64_t)N + (uint64_t)hi;
            const uint64_t kp  = (key * KEY_MUL) & KEY_MASK;
            h[k]     = (unsigned)(kp >> 12);            // top 22 bits
            vbase[k] = (((unsigned)(kp & 0xFFFu)) + 1u) << 10;
            old[k]   = act[k] ? atomicCAS(&g_hash[h[k]], 0u, vbase[k]) : 1u;
        }

        // Phase 4: resolve rare collisions (displacement encoded in value)
        bool win[UB];
        #pragma unroll
        for (int k = 0; k < UB; k++) {
            win[k] = false;
            if (act[k]) {
                unsigned o = old[k];
                unsigned d = 0;
                while (o != 0u && o != (vbase[k] | d)) {
                    d++;
                    const unsigned slot = (h[k] + d) & (TAB_SIZE - 1);
                    o = atomicCAS(&g_hash[slot], 0u, vbase[k] | d);
                }
                win[k] = (o == 0u);
            }
        }

        // Phase 5: adjacency-slot allocation via returning cnt atomicAdd.
        #pragma unroll
        for (int k = 0; k < UB; k++) {
            if (win[k]) {
                if (pa[k] < 0) {
                    const int slot = atomicAdd(&g_cnt[a[k]], 1);
                    if (slot < ADJ_DEG) g_adj[a[k] * ADJ_DEG + slot] = pb[k];
                }
                if (pb[k] < 0) {
                    const int slot = atomicAdd(&g_cnt[b[k]], 1);
                    if (slot < ADJ_DEG) g_adj[b[k] * ADJ_DEG + slot] = pa[k];
                }
            }
        }
    }
}

// 16 lanes per node: missing -> int4-walk adjacency row, accumulate present
// sources, write mean (or zeros) once, non-atomically.
__global__ void gather_kernel(const float4* __restrict__ xa4,
                              float4* __restrict__ out4,
                              int N, int Cv) {
    const int lane = threadIdx.x & 31;
    const int li   = lane & 15;
    const int sub  = lane >> 4;
    const int warp = (blockIdx.x * blockDim.x + threadIdx.x) >> 5;
    const int t = warp * 2 + sub;
    if (t >= N) return;
    if (g_pos[t] >= 0) return;

    const int cnt = g_cnt[t];
    const int m = min(cnt, ADJ_DEG);
    const int4* row = reinterpret_cast<const int4*>(&g_adj[t * ADJ_DEG]);

    float4 acc = make_float4(0.f, 0.f, 0.f, 0.f);
    for (int i = 0; i < m; i += 4) {
        const int4 q = row[i >> 2];
        float4 v0 = make_float4(0.f,0.f,0.f,0.f), v1 = v0, v2 = v0, v3 = v0;
        if (q.x >= 0)              v0 = xa4[(size_t)q.x * Cv + li];
        if (i + 1 < m && q.y >= 0) v1 = xa4[(size_t)q.y * Cv + li];
        if (i + 2 < m && q.z >= 0) v2 = xa4[(size_t)q.z * Cv + li];
        if (i + 3 < m && q.w >= 0) v3 = xa4[(size_t)q.w * Cv + li];
        acc.x += (v0.x + v1.x) + (v2.x + v3.x);
        acc.y += (v0.y + v1.y) + (v2.y + v3.y);
        acc.z += (v0.z + v1.z) + (v2.z + v3.z);
        acc.w += (v0.w + v1.w) + (v2.w + v3.w);
    }
    const float inv = (cnt > 0) ? 1.0f / (float)cnt : 0.0f;
    acc.x *= inv; acc.y *= inv; acc.z *= inv; acc.w *= inv;
    out4[(size_t)t * Cv + li] = acc;
}

extern "C" void kernel_launch(void* const* d_in, const int* in_sizes, int n_in,
                              void* d_out, int out_size) {
    const float* xa   = (const float*)d_in[0];   // [P, C] f32
    const int*   perm = (const int*)d_in[1];     // [P]
    const int*   ei   = (const int*)d_in[2];     // [2, E]
    (void)n_in;

    const int P  = in_sizes[1];
    const int C  = in_sizes[0] / P;              // 64
    const int Cv = C / 4;                        // 16
    const int E  = in_sizes[2] / 2;
    const int N  = out_size / C;                 // 100000
    float* out = (float*)d_out;

    clear_kernel<<<2048, 256>>>(N);

    {
        const int work = P * Cv;
        scatter_kernel<<<(work + 255) / 256, 256>>>(
            (const float4*)xa, perm, (float4*)out, P, Cv);
    }

    edge_kernel<<<EDGE_BLOCKS, EDGE_THREADS>>>(ei, ei + E, E, N);

    {
        const int work = N * 16;                 // 16 lanes per node
        gather_kernel<<<(work + 255) / 256, 256>>>(
            (const float4*)xa, (float4*)out, N, Cv);
    }
}

// round 11
// speedup vs baseline: 1.2364x; 1.2364x over previous
#include <cuda_runtime.h>
#include <stdint.h>

// ---------------------------------------------------------------------------
// AdaptiveUnpooling v11:
//   - edge path: EXACT v8 revert (64-bit canonical CAS, 32MB table, UB=4,
//     exact-wave grid, lb(256,5)). The 32-bit quotient hash regressed twice
//     (R9, R10) -> abandoned.
//   - compacted missing-node list (N-P entries, known on host).
//   - gather: one warp per missing node, TWO parallel adjacency chains
//     (half-warps walk alternate int4 groups), shfl combine, one store.
// ---------------------------------------------------------------------------

#define TAB_BITS 22
#define TAB_SIZE (1u << TAB_BITS)      // 4M slots * 8B = 32MB (L2-resident)
#define MAX_N    131072
#define ADJ_DEG  96
#define UB       4
#define EDGE_BLOCKS  740               // 148 SMs * 5 blocks/SM
#define EDGE_THREADS 256

__device__ unsigned long long g_hash[TAB_SIZE];
__device__ int g_cnt[MAX_N];
__device__ int g_pos[MAX_N];
__device__ int g_adj[MAX_N * ADJ_DEG];
__device__ int g_miss_count;
__device__ int g_miss[MAX_N];

__device__ __forceinline__ uint64_t mix64(uint64_t x) {
    x ^= x >> 33; x *= 0xff51afd7ed558ccdULL;
    x ^= x >> 33; x *= 0xc4ceb9fe1a85ec53ULL;
    x ^= x >> 33;
    return x;
}

__global__ void clear_kernel(int N) {
    const int stride = gridDim.x * blockDim.x;
    const int tid = blockIdx.x * blockDim.x + threadIdx.x;
    ulonglong2* h2 = reinterpret_cast<ulonglong2*>(g_hash);
    for (unsigned i = tid; i < TAB_SIZE / 2; i += stride)
        h2[i] = make_ulonglong2(0ULL, 0ULL);
    for (int i = tid; i < N; i += stride) { g_cnt[i] = 0; g_pos[i] = -1; }
    if (tid == 0) g_miss_count = 0;
}

__global__ void pos_kernel(const int* __restrict__ perm, int P) {
    const int i = blockIdx.x * blockDim.x + threadIdx.x;
    if (i < P) g_pos[perm[i]] = i;
}

// Compact list of missing nodes (pos < 0). Warp-aggregated append.
__global__ void miss_kernel(int N) {
    const int i = blockIdx.x * blockDim.x + threadIdx.x;
    const bool want = (i < N) && (g_pos[i] < 0);
    const unsigned bal = __ballot_sync(0xffffffffu, want);
    if (bal == 0u) return;
    const int lane = threadIdx.x & 31;
    const int leader = __ffs(bal) - 1;
    int base = 0;
    if (lane == leader) base = atomicAdd(&g_miss_count, __popc(bal));
    base = __shfl_sync(0xffffffffu, base, leader);
    if (want) g_miss[base + __popc(bal & ((1u << lane) - 1u))] = i;
}

// Copy present rows only: out[perm[r]] = xa[r].
__global__ void scatter_kernel(const float4* __restrict__ x4,
                               const int* __restrict__ perm,
                               float4* __restrict__ out4,
                               int P, int Cv) {
    const int gtid = blockIdx.x * blockDim.x + threadIdx.x;
    const int r = gtid / Cv;
    const int c = gtid - r * Cv;
    if (r < P)
        out4[(size_t)perm[r] * Cv + c] = x4[(size_t)r * Cv + c];
}

// UB edges per batch per thread, phased for MLP; exact-wave grid-stride.
__global__ void __launch_bounds__(EDGE_THREADS, 5)
edge_kernel(const int* __restrict__ e0,
            const int* __restrict__ e1,
            int E, int N) {
    const int tid = blockIdx.x * blockDim.x + threadIdx.x;
    const int TOT = gridDim.x * blockDim.x;
    const int step = TOT * UB;

    for (int base = tid; base < E; base += step) {
        int a[UB], b[UB], pa[UB], pb[UB];
        bool act[UB];

        // Phase 1: coalesced edge loads
        #pragma unroll
        for (int k = 0; k < UB; k++) {
            const int j = base + k * TOT;
            const bool v = (j < E);
            act[k] = v;
            a[k] = v ? e0[j] : 0;
            b[k] = v ? e1[j] : 1;
        }

        // Phase 2: independent pos loads
        #pragma unroll
        for (int k = 0; k < UB; k++) {
            act[k] = act[k] && (a[k] != b[k]);
            pa[k] = act[k] ? g_pos[a[k]] : 0;
            pb[k] = act[k] ? g_pos[b[k]] : 0;
            act[k] = act[k] && ((pa[k] < 0) || (pb[k] < 0));
        }

        // Phase 3: canonical keys + batched first-probe CAS
        unsigned h[UB];
        unsigned long long old[UB];
        #pragma unroll
        for (int k = 0; k < UB; k++) {
            const int lo = min(a[k], b[k]), hi = max(a[k], b[k]);
            const uint64_t key = (uint64_t)lo * (uint64_t)N + (uint64_t)hi + 1ULL;
            h[k] = (unsigned)mix64(key) & (TAB_SIZE - 1);
            old[k] = act[k] ? atomicCAS(&g_hash[h[k]], 0ULL, key) : 1ULL;
        }

        // Phase 4: resolve rare collisions
        bool win[UB];
        #pragma unroll
        for (int k = 0; k < UB; k++) {
            win[k] = false;
            if (act[k]) {
                const int lo = min(a[k], b[k]), hi = max(a[k], b[k]);
                const uint64_t key = (uint64_t)lo * (uint64_t)N + (uint64_t)hi + 1ULL;
                unsigned long long o = old[k];
                unsigned hh = h[k];
                while (o != 0ULL && o != key) {
                    hh = (hh + 1) & (TAB_SIZE - 1);
                    o = atomicCAS(&g_hash[hh], 0ULL, key);
                }
                win[k] = (o == 0ULL);
            }
        }

        // Phase 5: adjacency-slot allocation via returning cnt atomicAdd.
        #pragma unroll
        for (int k = 0; k < UB; k++) {
            if (win[k]) {
                if (pa[k] < 0) {
                    const int slot = atomicAdd(&g_cnt[a[k]], 1);
                    if (slot < ADJ_DEG) g_adj[a[k] * ADJ_DEG + slot] = pb[k];
                }
                if (pb[k] < 0) {
                    const int slot = atomicAdd(&g_cnt[b[k]], 1);
                    if (slot < ADJ_DEG) g_adj[b[k] * ADJ_DEG + slot] = pa[k];
                }
            }
        }
    }
}

// One warp per missing node. Half-warps walk alternate int4 adjacency groups
// (two parallel chains), accumulate features, shfl-combine, single store.
__global__ void gather_kernel(const float4* __restrict__ xa4,
                              float4* __restrict__ out4,
                              int M, int Cv) {
    const int lane = threadIdx.x & 31;
    const int li   = lane & 15;              // float4 column within row
    const int half = lane >> 4;              // 0 or 1: which chain
    const int w = (blockIdx.x * blockDim.x + threadIdx.x) >> 5;
    if (w >= M) return;                      // whole warp exits together

    const int t   = g_miss[w];
    const int cnt = g_cnt[t];
    const int m   = min(cnt, ADJ_DEG);
    const int4* row = reinterpret_cast<const int4*>(&g_adj[t * ADJ_DEG]);

    float4 acc = make_float4(0.f, 0.f, 0.f, 0.f);
    for (int g = half; g * 4 < m; g += 2) {  // alternate groups per half
        const int4 q = row[g];
        const int bse = g * 4;
        float4 v0 = make_float4(0.f,0.f,0.f,0.f), v1 = v0, v2 = v0, v3 = v0;
        if (q.x >= 0)                v0 = xa4[(size_t)q.x * Cv + li];
        if (bse + 1 < m && q.y >= 0) v1 = xa4[(size_t)q.y * Cv + li];
        if (bse + 2 < m && q.z >= 0) v2 = xa4[(size_t)q.z * Cv + li];
        if (bse + 3 < m && q.w >= 0) v3 = xa4[(size_t)q.w * Cv + li];
        acc.x += (v0.x + v1.x) + (v2.x + v3.x);
        acc.y += (v0.y + v1.y) + (v2.y + v3.y);
        acc.z += (v0.z + v1.z) + (v2.z + v3.z);
        acc.w += (v0.w + v1.w) + (v2.w + v3.w);
    }

    // Combine the two half-warp chains (lane i <-> lane i^16).
    acc.x += __shfl_xor_sync(0xffffffffu, acc.x, 16);
    acc.y += __shfl_xor_sync(0xffffffffu, acc.y, 16);
    acc.z += __shfl_xor_sync(0xffffffffu, acc.z, 16);
    acc.w += __shfl_xor_sync(0xffffffffu, acc.w, 16);

    if (half == 0) {
        const float inv = (cnt > 0) ? 1.0f / (float)cnt : 0.0f;
        acc.x *= inv; acc.y *= inv; acc.z *= inv; acc.w *= inv;
        out4[(size_t)t * Cv + li] = acc;
    }
}

extern "C" void kernel_launch(void* const* d_in, const int* in_sizes, int n_in,
                              void* d_out, int out_size) {
    const float* xa   = (const float*)d_in[0];   // [P, C] f32
    const int*   perm = (const int*)d_in[1];     // [P]
    const int*   ei   = (const int*)d_in[2];     // [2, E]
    (void)n_in;

    const int P  = in_sizes[1];
    const int C  = in_sizes[0] / P;              // 64
    const int Cv = C / 4;                        // 16
    const int E  = in_sizes[2] / 2;
    const int N  = out_size / C;                 // 100000
    const int M  = N - P;                        // missing nodes (exact)
    float* out = (float*)d_out;

    clear_kernel<<<1024, 256>>>(N);
    pos_kernel<<<(P + 255) / 256, 256>>>(perm, P);
    miss_kernel<<<(N + 255) / 256, 256>>>(N);

    {
        const int work = P * Cv;
        scatter_kernel<<<(work + 255) / 256, 256>>>(
            (const float4*)xa, perm, (float4*)out, P, Cv);
    }

    edge_kernel<<<EDGE_BLOCKS, EDGE_THREADS>>>(ei, ei + E, E, N);

    {
        const long long work = (long long)M * 32; // one warp per missing node
        const int blocks = (int)((work + 255) / 256);
        gather_kernel<<<blocks, 256>>>((const float4*)xa, (float4*)out, M, Cv);
    }
}

// round 12
// speedup vs baseline: 1.2873x; 1.0411x over previous
#include <cuda_runtime.h>
#include <stdint.h>

// ---------------------------------------------------------------------------
// AdaptiveUnpooling v12 (= v11 with pos_kernel folded into scatter_kernel):
//   - edge: 64-bit canonical CAS, 32MB table, UB=4, exact-wave grid, lb(256,5).
//   - scatter copies present rows AND writes g_pos (c==0 lane per row).
//   - compacted missing-node list, then warp-per-node gather with two
//     parallel adjacency chains and a single non-atomic store.
//   - strictly serial single-stream spine (overlap robs edge occupancy).
// ---------------------------------------------------------------------------

#define TAB_BITS 22
#define TAB_SIZE (1u << TAB_BITS)      // 4M slots * 8B = 32MB (L2-resident)
#define MAX_N    131072
#define ADJ_DEG  96
#define UB       4
#define EDGE_BLOCKS  740               // 148 SMs * 5 blocks/SM
#define EDGE_THREADS 256

__device__ unsigned long long g_hash[TAB_SIZE];
__device__ int g_cnt[MAX_N];
__device__ int g_pos[MAX_N];
__device__ int g_adj[MAX_N * ADJ_DEG];
__device__ int g_miss_count;
__device__ int g_miss[MAX_N];

__device__ __forceinline__ uint64_t mix64(uint64_t x) {
    x ^= x >> 33; x *= 0xff51afd7ed558ccdULL;
    x ^= x >> 33; x *= 0xc4ceb9fe1a85ec53ULL;
    x ^= x >> 33;
    return x;
}

__global__ void clear_kernel(int N) {
    const int stride = gridDim.x * blockDim.x;
    const int tid = blockIdx.x * blockDim.x + threadIdx.x;
    ulonglong2* h2 = reinterpret_cast<ulonglong2*>(g_hash);
    for (unsigned i = tid; i < TAB_SIZE / 2; i += stride)
        h2[i] = make_ulonglong2(0ULL, 0ULL);
    for (int i = tid; i < N; i += stride) { g_cnt[i] = 0; g_pos[i] = -1; }
    if (tid == 0) g_miss_count = 0;
}

// Copy present rows AND build pos map (c==0 lane of each row writes pos).
__global__ void scatter_kernel(const float4* __restrict__ x4,
                               const int* __restrict__ perm,
                               float4* __restrict__ out4,
                               int P, int Cv) {
    const int gtid = blockIdx.x * blockDim.x + threadIdx.x;
    const int r = gtid / Cv;
    const int c = gtid - r * Cv;
    if (r < P) {
        const int node = perm[r];
        if (c == 0) g_pos[node] = r;
        out4[(size_t)node * Cv + c] = x4[(size_t)r * Cv + c];
    }
}

// Compact list of missing nodes (pos < 0). Warp-aggregated append.
__global__ void miss_kernel(int N) {
    const int i = blockIdx.x * blockDim.x + threadIdx.x;
    const bool want = (i < N) && (g_pos[i] < 0);
    const unsigned bal = __ballot_sync(0xffffffffu, want);
    if (bal == 0u) return;
    const int lane = threadIdx.x & 31;
    const int leader = __ffs(bal) - 1;
    int base = 0;
    if (lane == leader) base = atomicAdd(&g_miss_count, __popc(bal));
    base = __shfl_sync(0xffffffffu, base, leader);
    if (want) g_miss[base + __popc(bal & ((1u << lane) - 1u))] = i;
}

// UB edges per batch per thread, phased for MLP; exact-wave grid-stride.
__global__ void __launch_bounds__(EDGE_THREADS, 5)
edge_kernel(const int* __restrict__ e0,
            const int* __restrict__ e1,
            int E, int N) {
    const int tid = blockIdx.x * blockDim.x + threadIdx.x;
    const int TOT = gridDim.x * blockDim.x;
    const int step = TOT * UB;

    for (int base = tid; base < E; base += step) {
        int a[UB], b[UB], pa[UB], pb[UB];
        bool act[UB];

        // Phase 1: coalesced edge loads
        #pragma unroll
        for (int k = 0; k < UB; k++) {
            const int j = base + k * TOT;
            const bool v = (j < E);
            act[k] = v;
            a[k] = v ? e0[j] : 0;
            b[k] = v ? e1[j] : 1;
        }

        // Phase 2: independent pos loads
        #pragma unroll
        for (int k = 0; k < UB; k++) {
            act[k] = act[k] && (a[k] != b[k]);
            pa[k] = act[k] ? g_pos[a[k]] : 0;
            pb[k] = act[k] ? g_pos[b[k]] : 0;
            act[k] = act[k] && ((pa[k] < 0) || (pb[k] < 0));
        }

        // Phase 3: canonical keys + batched first-probe CAS
        unsigned h[UB];
        unsigned long long old[UB];
        #pragma unroll
        for (int k = 0; k < UB; k++) {
            const int lo = min(a[k], b[k]), hi = max(a[k], b[k]);
            const uint64_t key = (uint64_t)lo * (uint64_t)N + (uint64_t)hi + 1ULL;
            h[k] = (unsigned)mix64(key) & (TAB_SIZE - 1);
            old[k] = act[k] ? atomicCAS(&g_hash[h[k]], 0ULL, key) : 1ULL;
        }

        // Phase 4: resolve rare collisions
        bool win[UB];
        #pragma unroll
        for (int k = 0; k < UB; k++) {
            win[k] = false;
            if (act[k]) {
                const int lo = min(a[k], b[k]), hi = max(a[k], b[k]);
                const uint64_t key = (uint64_t)lo * (uint64_t)N + (uint64_t)hi + 1ULL;
                unsigned long long o = old[k];
                unsigned hh = h[k];
                while (o != 0ULL && o != key) {
                    hh = (hh + 1) & (TAB_SIZE - 1);
                    o = atomicCAS(&g_hash[hh], 0ULL, key);
                }
                win[k] = (o == 0ULL);
            }
        }

        // Phase 5: adjacency-slot allocation via returning cnt atomicAdd.
        #pragma unroll
        for (int k = 0; k < UB; k++) {
            if (win[k]) {
                if (pa[k] < 0) {
                    const int slot = atomicAdd(&g_cnt[a[k]], 1);
                    if (slot < ADJ_DEG) g_adj[a[k] * ADJ_DEG + slot] = pb[k];
                }
                if (pb[k] < 0) {
                    const int slot = atomicAdd(&g_cnt[b[k]], 1);
                    if (slot < ADJ_DEG) g_adj[b[k] * ADJ_DEG + slot] = pa[k];
                }
            }
        }
    }
}

// One warp per missing node. Half-warps walk alternate int4 adjacency groups
// (two parallel chains), accumulate features, shfl-combine, single store.
__global__ void gather_kernel(const float4* __restrict__ xa4,
                              float4* __restrict__ out4,
                              int M, int Cv) {
    const int lane = threadIdx.x & 31;
    const int li   = lane & 15;              // float4 column within row
    const int half = lane >> 4;              // 0 or 1: which chain
    const int w = (blockIdx.x * blockDim.x + threadIdx.x) >> 5;
    if (w >= M) return;                      // whole warp exits together

    const int t   = g_miss[w];
    const int cnt = g_cnt[t];
    const int m   = min(cnt, ADJ_DEG);
    const int4* row = reinterpret_cast<const int4*>(&g_adj[t * ADJ_DEG]);

    float4 acc = make_float4(0.f, 0.f, 0.f, 0.f);
    for (int g = half; g * 4 < m; g += 2) {  // alternate groups per half
        const int4 q = row[g];
        const int bse = g * 4;
        float4 v0 = make_float4(0.f,0.f,0.f,0.f), v1 = v0, v2 = v0, v3 = v0;
        if (q.x >= 0)                v0 = xa4[(size_t)q.x * Cv + li];
        if (bse + 1 < m && q.y >= 0) v1 = xa4[(size_t)q.y * Cv + li];
        if (bse + 2 < m && q.z >= 0) v2 = xa4[(size_t)q.z * Cv + li];
        if (bse + 3 < m && q.w >= 0) v3 = xa4[(size_t)q.w * Cv + li];
        acc.x += (v0.x + v1.x) + (v2.x + v3.x);
        acc.y += (v0.y + v1.y) + (v2.y + v3.y);
        acc.z += (v0.z + v1.z) + (v2.z + v3.z);
        acc.w += (v0.w + v1.w) + (v2.w + v3.w);
    }

    // Combine the two half-warp chains (lane i <-> lane i^16).
    acc.x += __shfl_xor_sync(0xffffffffu, acc.x, 16);
    acc.y += __shfl_xor_sync(0xffffffffu, acc.y, 16);
    acc.z += __shfl_xor_sync(0xffffffffu, acc.z, 16);
    acc.w += __shfl_xor_sync(0xffffffffu, acc.w, 16);

    if (half == 0) {
        const float inv = (cnt > 0) ? 1.0f / (float)cnt : 0.0f;
        acc.x *= inv; acc.y *= inv; acc.z *= inv; acc.w *= inv;
        out4[(size_t)t * Cv + li] = acc;
    }
}

extern "C" void kernel_launch(void* const* d_in, const int* in_sizes, int n_in,
                              void* d_out, int out_size) {
    const float* xa   = (const float*)d_in[0];   // [P, C] f32
    const int*   perm = (const int*)d_in[1];     // [P]
    const int*   ei   = (const int*)d_in[2];     // [2, E]
    (void)n_in;

    const int P  = in_sizes[1];
    const int C  = in_sizes[0] / P;              // 64
    const int Cv = C / 4;                        // 16
    const int E  = in_sizes[2] / 2;
    const int N  = out_size / C;                 // 100000
    const int M  = N - P;                        // missing nodes (exact)
    float* out = (float*)d_out;

    clear_kernel<<<2048, 256>>>(N);

    {
        const int work = P * Cv;
        scatter_kernel<<<(work + 255) / 256, 256>>>(
            (const float4*)xa, perm, (float4*)out, P, Cv);
    }

    miss_kernel<<<(N + 255) / 256, 256>>>(N);

    edge_kernel<<<EDGE_BLOCKS, EDGE_THREADS>>>(ei, ei + E, E, N);

    {
        const long long work = (long long)M * 32; // one warp per missing node
        const int blocks = (int)((work + 255) / 256);
        gather_kernel<<<blocks, 256>>>((const float4*)xa, (float4*)out, M, Cv);
    }
}

// round 13
// speedup vs baseline: 1.3344x; 1.0366x over previous
#include <cuda_runtime.h>
#include <stdint.h>

// ---------------------------------------------------------------------------
// AdaptiveUnpooling v13 (= v12 + shared-memory presence bitmap in edge):
//   - presence bitmap (1 bit/node, 12.5KB) loaded into SMEM per edge block:
//     presence checks become LDS instead of random L2 loads; g_pos is read
//     only post-win for present other-endpoints (~4x fewer pos loads).
//   - edge: 64-bit canonical CAS, 32MB table, UB=4, exact-wave grid, lb(256,5).
//   - scatter copies present rows, writes g_pos AND sets bitmap bits.
//   - compacted missing-node list; warp-per-node gather (two chains).
//   - strictly serial single-stream spine.
// ---------------------------------------------------------------------------

#define TAB_BITS 22
#define TAB_SIZE (1u << TAB_BITS)      // 4M slots * 8B = 32MB (L2-resident)
#define MAX_N    131072
#define BM_WORDS (MAX_N / 32)          // 4096 words = 16KB
#define ADJ_DEG  96
#define UB       4
#define EDGE_BLOCKS  740               // 148 SMs * 5 blocks/SM
#define EDGE_THREADS 256

__device__ unsigned long long g_hash[TAB_SIZE];
__device__ int g_cnt[MAX_N];
__device__ int g_pos[MAX_N];
__device__ unsigned g_bitmap[BM_WORDS];   // bit set => node present
__device__ int g_adj[MAX_N * ADJ_DEG];
__device__ int g_miss_count;
__device__ int g_miss[MAX_N];

__device__ __forceinline__ uint64_t mix64(uint64_t x) {
    x ^= x >> 33; x *= 0xff51afd7ed558ccdULL;
    x ^= x >> 33; x *= 0xc4ceb9fe1a85ec53ULL;
    x ^= x >> 33;
    return x;
}

__global__ void clear_kernel(int N) {
    const int stride = gridDim.x * blockDim.x;
    const int tid = blockIdx.x * blockDim.x + threadIdx.x;
    ulonglong2* h2 = reinterpret_cast<ulonglong2*>(g_hash);
    for (unsigned i = tid; i < TAB_SIZE / 2; i += stride)
        h2[i] = make_ulonglong2(0ULL, 0ULL);
    for (int i = tid; i < N; i += stride) { g_cnt[i] = 0; g_pos[i] = -1; }
    for (int i = tid; i < BM_WORDS; i += stride) g_bitmap[i] = 0u;
    if (tid == 0) g_miss_count = 0;
}

// Copy present rows, build pos map and presence bitmap.
__global__ void scatter_kernel(const float4* __restrict__ x4,
                               const int* __restrict__ perm,
                               float4* __restrict__ out4,
                               int P, int Cv) {
    const int gtid = blockIdx.x * blockDim.x + threadIdx.x;
    const int r = gtid / Cv;
    const int c = gtid - r * Cv;
    if (r < P) {
        const int node = perm[r];
        if (c == 0) {
            g_pos[node] = r;
            atomicOr(&g_bitmap[node >> 5], 1u << (node & 31));
        }
        out4[(size_t)node * Cv + c] = x4[(size_t)r * Cv + c];
    }
}

// Compact list of missing nodes (pos < 0). Warp-aggregated append.
__global__ void miss_kernel(int N) {
    const int i = blockIdx.x * blockDim.x + threadIdx.x;
    const bool want = (i < N) && (g_pos[i] < 0);
    const unsigned bal = __ballot_sync(0xffffffffu, want);
    if (bal == 0u) return;
    const int lane = threadIdx.x & 31;
    const int leader = __ffs(bal) - 1;
    int base = 0;
    if (lane == leader) base = atomicAdd(&g_miss_count, __popc(bal));
    base = __shfl_sync(0xffffffffu, base, leader);
    if (want) g_miss[base + __popc(bal & ((1u << lane) - 1u))] = i;
}

// UB edges per batch per thread; presence via SMEM bitmap; pos loaded only
// post-win for present other-endpoints.
__global__ void __launch_bounds__(EDGE_THREADS, 5)
edge_kernel(const int* __restrict__ e0,
            const int* __restrict__ e1,
            int E, int N) {
    __shared__ unsigned s_bm[BM_WORDS];
    const int nw = (N + 31) >> 5;
    for (int i = threadIdx.x; i < nw; i += blockDim.x) s_bm[i] = g_bitmap[i];
    __syncthreads();

    const int tid = blockIdx.x * blockDim.x + threadIdx.x;
    const int TOT = gridDim.x * blockDim.x;
    const int step = TOT * UB;

    for (int base = tid; base < E; base += step) {
        int a[UB], b[UB];
        bool act[UB], ma[UB], mb[UB];

        // Phase 1: coalesced edge loads
        #pragma unroll
        for (int k = 0; k < UB; k++) {
            const int j = base + k * TOT;
            const bool v = (j < E);
            act[k] = v;
            a[k] = v ? e0[j] : 0;
            b[k] = v ? e1[j] : 1;
        }

        // Phase 2: presence checks from SMEM bitmap (fast)
        #pragma unroll
        for (int k = 0; k < UB; k++) {
            ma[k] = !((s_bm[a[k] >> 5] >> (a[k] & 31)) & 1u);  // a missing
            mb[k] = !((s_bm[b[k] >> 5] >> (b[k] & 31)) & 1u);  // b missing
            act[k] = act[k] && (a[k] != b[k]) && (ma[k] || mb[k]);
        }

        // Phase 3: canonical keys + batched first-probe CAS
        unsigned h[UB];
        unsigned long long old[UB];
        #pragma unroll
        for (int k = 0; k < UB; k++) {
            const int lo = min(a[k], b[k]), hi = max(a[k], b[k]);
            const uint64_t key = (uint64_t)lo * (uint64_t)N + (uint64_t)hi + 1ULL;
            h[k] = (unsigned)mix64(key) & (TAB_SIZE - 1);
            old[k] = act[k] ? atomicCAS(&g_hash[h[k]], 0ULL, key) : 1ULL;
        }

        // Phase 4: resolve rare collisions
        bool win[UB];
        #pragma unroll
        for (int k = 0; k < UB; k++) {
            win[k] = false;
            if (act[k]) {
                const int lo = min(a[k], b[k]), hi = max(a[k], b[k]);
                const uint64_t key = (uint64_t)lo * (uint64_t)N + (uint64_t)hi + 1ULL;
                unsigned long long o = old[k];
                unsigned hh = h[k];
                while (o != 0ULL && o != key) {
                    hh = (hh + 1) & (TAB_SIZE - 1);
                    o = atomicCAS(&g_hash[hh], 0ULL, key);
                }
                win[k] = (o == 0ULL);
            }
        }

        // Phase 5: adjacency-slot allocation; pos loaded only if other present.
        #pragma unroll
        for (int k = 0; k < UB; k++) {
            if (win[k]) {
                if (ma[k]) {
                    const int val = mb[k] ? -1 : g_pos[b[k]];
                    const int slot = atomicAdd(&g_cnt[a[k]], 1);
                    if (slot < ADJ_DEG) g_adj[a[k] * ADJ_DEG + slot] = val;
                }
                if (mb[k]) {
                    const int val = ma[k] ? -1 : g_pos[a[k]];
                    const int slot = atomicAdd(&g_cnt[b[k]], 1);
                    if (slot < ADJ_DEG) g_adj[b[k] * ADJ_DEG + slot] = val;
                }
            }
        }
    }
}

// One warp per missing node. Half-warps walk alternate int4 adjacency groups
// (two parallel chains), accumulate features, shfl-combine, single store.
__global__ void gather_kernel(const float4* __restrict__ xa4,
                              float4* __restrict__ out4,
                              int M, int Cv) {
    const int lane = threadIdx.x & 31;
    const int li   = lane & 15;
    const int half = lane >> 4;
    const int w = (blockIdx.x * blockDim.x + threadIdx.x) >> 5;
    if (w >= M) return;

    const int t   = g_miss[w];
    const int cnt = g_cnt[t];
    const int m   = min(cnt, ADJ_DEG);
    const int4* row = reinterpret_cast<const int4*>(&g_adj[t * ADJ_DEG]);

    float4 acc = make_float4(0.f, 0.f, 0.f, 0.f);
    for (int g = half; g * 4 < m; g += 2) {
        const int4 q = row[g];
        const int bse = g * 4;
        float4 v0 = make_float4(0.f,0.f,0.f,0.f), v1 = v0, v2 = v0, v3 = v0;
        if (q.x >= 0)                v0 = xa4[(size_t)q.x * Cv + li];
        if (bse + 1 < m && q.y >= 0) v1 = xa4[(size_t)q.y * Cv + li];
        if (bse + 2 < m && q.z >= 0) v2 = xa4[(size_t)q.z * Cv + li];
        if (bse + 3 < m && q.w >= 0) v3 = xa4[(size_t)q.w * Cv + li];
        acc.x += (v0.x + v1.x) + (v2.x + v3.x);
        acc.y += (v0.y + v1.y) + (v2.y + v3.y);
        acc.z += (v0.z + v1.z) + (v2.z + v3.z);
        acc.w += (v0.w + v1.w) + (v2.w + v3.w);
    }

    acc.x += __shfl_xor_sync(0xffffffffu, acc.x, 16);
    acc.y += __shfl_xor_sync(0xffffffffu, acc.y, 16);
    acc.z += __shfl_xor_sync(0xffffffffu, acc.z, 16);
    acc.w += __shfl_xor_sync(0xffffffffu, acc.w, 16);

    if (half == 0) {
        const float inv = (cnt > 0) ? 1.0f / (float)cnt : 0.0f;
        acc.x *= inv; acc.y *= inv; acc.z *= inv; acc.w *= inv;
        out4[(size_t)t * Cv + li] = acc;
    }
}

extern "C" void kernel_launch(void* const* d_in, const int* in_sizes, int n_in,
                              void* d_out, int out_size) {
    const float* xa   = (const float*)d_in[0];   // [P, C] f32
    const int*   perm = (const int*)d_in[1];     // [P]
    const int*   ei   = (const int*)d_in[2];     // [2, E]
    (void)n_in;

    const int P  = in_sizes[1];
    const int C  = in_sizes[0] / P;              // 64
    const int Cv = C / 4;                        // 16
    const int E  = in_sizes[2] / 2;
    const int N  = out_size / C;                 // 100000
    const int M  = N - P;                        // missing nodes (exact)
    float* out = (float*)d_out;

    clear_kernel<<<2048, 256>>>(N);

    {
        const int work = P * Cv;
        scatter_kernel<<<(work + 255) / 256, 256>>>(
            (const float4*)xa, perm, (float4*)out, P, Cv);
    }

    miss_kernel<<<(N + 255) / 256, 256>>>(N);

    edge_kernel<<<EDGE_BLOCKS, EDGE_THREADS>>>(ei, ei + E, E, N);

    {
        const long long work = (long long)M * 32;
        const int blocks = (int)((work + 255) / 256);
        gather_kernel<<<blocks, 256>>>((const float4*)xa, (float4*)out, M, Cv);
    }
}

// round 14
// speedup vs baseline: 1.3687x; 1.0257x over previous
#include <cuda_runtime.h>
#include <stdint.h>

// ---------------------------------------------------------------------------
// AdaptiveUnpooling v14 (= v13 with edge occupancy 5 -> 6 blocks/SM):
//   - presence bitmap (1 bit/node, 12.5KB) in SMEM for edge presence checks;
//     g_pos read only post-win for present other-endpoints.
//   - edge: 64-bit canonical CAS, 32MB table, UB=4, exact-wave grid,
//     __launch_bounds__(256,6) (regs<=42, +20% resident chains).
//   - scatter copies present rows, writes g_pos AND sets bitmap bits.
//   - compacted missing-node list; warp-per-node gather (two chains).
//   - strictly serial single-stream spine.
// ---------------------------------------------------------------------------

#define TAB_BITS 22
#define TAB_SIZE (1u << TAB_BITS)      // 4M slots * 8B = 32MB (L2-resident)
#define MAX_N    131072
#define BM_WORDS (MAX_N / 32)          // 4096 words = 16KB
#define ADJ_DEG  96
#define UB       4
#define EDGE_BLOCKS  888               // 148 SMs * 6 blocks/SM
#define EDGE_THREADS 256

__device__ unsigned long long g_hash[TAB_SIZE];
__device__ int g_cnt[MAX_N];
__device__ int g_pos[MAX_N];
__device__ unsigned g_bitmap[BM_WORDS];   // bit set => node present
__device__ int g_adj[MAX_N * ADJ_DEG];
__device__ int g_miss_count;
__device__ int g_miss[MAX_N];

__device__ __forceinline__ uint64_t mix64(uint64_t x) {
    x ^= x >> 33; x *= 0xff51afd7ed558ccdULL;
    x ^= x >> 33; x *= 0xc4ceb9fe1a85ec53ULL;
    x ^= x >> 33;
    return x;
}

__global__ void clear_kernel(int N) {
    const int stride = gridDim.x * blockDim.x;
    const int tid = blockIdx.x * blockDim.x + threadIdx.x;
    ulonglong2* h2 = reinterpret_cast<ulonglong2*>(g_hash);
    for (unsigned i = tid; i < TAB_SIZE / 2; i += stride)
        h2[i] = make_ulonglong2(0ULL, 0ULL);
    for (int i = tid; i < N; i += stride) { g_cnt[i] = 0; g_pos[i] = -1; }
    for (int i = tid; i < BM_WORDS; i += stride) g_bitmap[i] = 0u;
    if (tid == 0) g_miss_count = 0;
}

// Copy present rows, build pos map and presence bitmap.
__global__ void scatter_kernel(const float4* __restrict__ x4,
                               const int* __restrict__ perm,
                               float4* __restrict__ out4,
                               int P, int Cv) {
    const int gtid = blockIdx.x * blockDim.x + threadIdx.x;
    const int r = gtid / Cv;
    const int c = gtid - r * Cv;
    if (r < P) {
        const int node = perm[r];
        if (c == 0) {
            g_pos[node] = r;
            atomicOr(&g_bitmap[node >> 5], 1u << (node & 31));
        }
        out4[(size_t)node * Cv + c] = x4[(size_t)r * Cv + c];
    }
}

// Compact list of missing nodes (pos < 0). Warp-aggregated append.
__global__ void miss_kernel(int N) {
    const int i = blockIdx.x * blockDim.x + threadIdx.x;
    const bool want = (i < N) && (g_pos[i] < 0);
    const unsigned bal = __ballot_sync(0xffffffffu, want);
    if (bal == 0u) return;
    const int lane = threadIdx.x & 31;
    const int leader = __ffs(bal) - 1;
    int base = 0;
    if (lane == leader) base = atomicAdd(&g_miss_count, __popc(bal));
    base = __shfl_sync(0xffffffffu, base, leader);
    if (want) g_miss[base + __popc(bal & ((1u << lane) - 1u))] = i;
}

// UB edges per batch per thread; presence via SMEM bitmap; pos loaded only
// post-win for present other-endpoints.
__global__ void __launch_bounds__(EDGE_THREADS, 6)
edge_kernel(const int* __restrict__ e0,
            const int* __restrict__ e1,
            int E, int N) {
    __shared__ unsigned s_bm[BM_WORDS];
    const int nw = (N + 31) >> 5;
    for (int i = threadIdx.x; i < nw; i += blockDim.x) s_bm[i] = g_bitmap[i];
    __syncthreads();

    const int tid = blockIdx.x * blockDim.x + threadIdx.x;
    const int TOT = gridDim.x * blockDim.x;
    const int step = TOT * UB;

    for (int base = tid; base < E; base += step) {
        int a[UB], b[UB];
        bool act[UB], ma[UB], mb[UB];

        // Phase 1: coalesced edge loads
        #pragma unroll
        for (int k = 0; k < UB; k++) {
            const int j = base + k * TOT;
            const bool v = (j < E);
            act[k] = v;
            a[k] = v ? e0[j] : 0;
            b[k] = v ? e1[j] : 1;
        }

        // Phase 2: presence checks from SMEM bitmap (fast)
        #pragma unroll
        for (int k = 0; k < UB; k++) {
            ma[k] = !((s_bm[a[k] >> 5] >> (a[k] & 31)) & 1u);  // a missing
            mb[k] = !((s_bm[b[k] >> 5] >> (b[k] & 31)) & 1u);  // b missing
            act[k] = act[k] && (a[k] != b[k]) && (ma[k] || mb[k]);
        }

        // Phase 3: canonical keys + batched first-probe CAS
        unsigned h[UB];
        unsigned long long old[UB];
        #pragma unroll
        for (int k = 0; k < UB; k++) {
            const int lo = min(a[k], b[k]), hi = max(a[k], b[k]);
            const uint64_t key = (uint64_t)lo * (uint64_t)N + (uint64_t)hi + 1ULL;
            h[k] = (unsigned)mix64(key) & (TAB_SIZE - 1);
            old[k] = act[k] ? atomicCAS(&g_hash[h[k]], 0ULL, key) : 1ULL;
        }

        // Phase 4: resolve rare collisions
        bool win[UB];
        #pragma unroll
        for (int k = 0; k < UB; k++) {
            win[k] = false;
            if (act[k]) {
                const int lo = min(a[k], b[k]), hi = max(a[k], b[k]);
                const uint64_t key = (uint64_t)lo * (uint64_t)N + (uint64_t)hi + 1ULL;
                unsigned long long o = old[k];
                unsigned hh = h[k];
                while (o != 0ULL && o != key) {
                    hh = (hh + 1) & (TAB_SIZE - 1);
                    o = atomicCAS(&g_hash[hh], 0ULL, key);
                }
                win[k] = (o == 0ULL);
            }
        }

        // Phase 5: adjacency-slot allocation; pos loaded only if other present.
        #pragma unroll
        for (int k = 0; k < UB; k++) {
            if (win[k]) {
                if (ma[k]) {
                    const int val = mb[k] ? -1 : g_pos[b[k]];
                    const int slot = atomicAdd(&g_cnt[a[k]], 1);
                    if (slot < ADJ_DEG) g_adj[a[k] * ADJ_DEG + slot] = val;
                }
                if (mb[k]) {
                    const int val = ma[k] ? -1 : g_pos[a[k]];
                    const int slot = atomicAdd(&g_cnt[b[k]], 1);
                    if (slot < ADJ_DEG) g_adj[b[k] * ADJ_DEG + slot] = val;
                }
            }
        }
    }
}

// One warp per missing node. Half-warps walk alternate int4 adjacency groups
// (two parallel chains), accumulate features, shfl-combine, single store.
__global__ void gather_kernel(const float4* __restrict__ xa4,
                              float4* __restrict__ out4,
                              int M, int Cv) {
    const int lane = threadIdx.x & 31;
    const int li   = lane & 15;
    const int half = lane >> 4;
    const int w = (blockIdx.x * blockDim.x + threadIdx.x) >> 5;
    if (w >= M) return;

    const int t   = g_miss[w];
    const int cnt = g_cnt[t];
    const int m   = min(cnt, ADJ_DEG);
    const int4* row = reinterpret_cast<const int4*>(&g_adj[t * ADJ_DEG]);

    float4 acc = make_float4(0.f, 0.f, 0.f, 0.f);
    for (int g = half; g * 4 < m; g += 2) {
        const int4 q = row[g];
        const int bse = g * 4;
        float4 v0 = make_float4(0.f,0.f,0.f,0.f), v1 = v0, v2 = v0, v3 = v0;
        if (q.x >= 0)                v0 = xa4[(size_t)q.x * Cv + li];
        if (bse + 1 < m && q.y >= 0) v1 = xa4[(size_t)q.y * Cv + li];
        if (bse + 2 < m && q.z >= 0) v2 = xa4[(size_t)q.z * Cv + li];
        if (bse + 3 < m && q.w >= 0) v3 = xa4[(size_t)q.w * Cv + li];
        acc.x += (v0.x + v1.x) + (v2.x + v3.x);
        acc.y += (v0.y + v1.y) + (v2.y + v3.y);
        acc.z += (v0.z + v1.z) + (v2.z + v3.z);
        acc.w += (v0.w + v1.w) + (v2.w + v3.w);
    }

    acc.x += __shfl_xor_sync(0xffffffffu, acc.x, 16);
    acc.y += __shfl_xor_sync(0xffffffffu, acc.y, 16);
    acc.z += __shfl_xor_sync(0xffffffffu, acc.z, 16);
    acc.w += __shfl_xor_sync(0xffffffffu, acc.w, 16);

    if (half == 0) {
        const float inv = (cnt > 0) ? 1.0f / (float)cnt : 0.0f;
        acc.x *= inv; acc.y *= inv; acc.z *= inv; acc.w *= inv;
        out4[(size_t)t * Cv + li] = acc;
    }
}

extern "C" void kernel_launch(void* const* d_in, const int* in_sizes, int n_in,
                              void* d_out, int out_size) {
    const float* xa   = (const float*)d_in[0];   // [P, C] f32
    const int*   perm = (const int*)d_in[1];     // [P]
    const int*   ei   = (const int*)d_in[2];     // [2, E]
    (void)n_in;

    const int P  = in_sizes[1];
    const int C  = in_sizes[0] / P;              // 64
    const int Cv = C / 4;                        // 16
    const int E  = in_sizes[2] / 2;
    const int N  = out_size / C;                 // 100000
    const int M  = N - P;                        // missing nodes (exact)
    float* out = (float*)d_out;

    clear_kernel<<<2048, 256>>>(N);

    {
        const int work = P * Cv;
        scatter_kernel<<<(work + 255) / 256, 256>>>(
            (const float4*)xa, perm, (float4*)out, P, Cv);
    }

    miss_kernel<<<(N + 255) / 256, 256>>>(N);

    edge_kernel<<<EDGE_BLOCKS, EDGE_THREADS>>>(ei, ei + E, E, N);

    {
        const long long work = (long long)M * 32;
        const int blocks = (int)((work + 255) / 256);
        gather_kernel<<<blocks, 256>>>((const float4*)xa, (float4*)out, M, Cv);
    }
}

// round 15
// speedup vs baseline: 1.5656x; 1.1439x over previous
#include <cuda_runtime.h>
#include <stdint.h>

// ---------------------------------------------------------------------------
// AdaptiveUnpooling v15:
//   - packed dual counter: g_cnt word = (present_cnt << 16) | total_cnt.
//     Missing-source wins bump total only (NO adj store); present-source
//     wins allocate a dense adj slot via (old >> 16). ~0.6M fewer random
//     stores in edge; gather reads only present entries (no guards).
//   - edge: 64-bit canonical CAS, 32MB table, UB=4, SMEM presence bitmap,
//     lb(256,6), exact-wave 888-block grid.
//   - pre-edge fork: side stream (clear_small -> scatter -> miss) overlaps
//     main-stream clear_table; JOINED BEFORE edge (nothing co-runs w/ edge).
//   - warp-per-missing-node gather, two parallel chains, one store.
// ---------------------------------------------------------------------------

#define TAB_BITS 22
#define TAB_SIZE (1u << TAB_BITS)      // 4M slots * 8B = 32MB (L2-resident)
#define MAX_N    131072
#define BM_WORDS (MAX_N / 32)
#define ADJ_DEG  96
#define UB       4
#define EDGE_BLOCKS  888               // 148 SMs * 6 blocks/SM
#define EDGE_THREADS 256

__device__ unsigned long long g_hash[TAB_SIZE];
__device__ unsigned g_cnt[MAX_N];      // (present_cnt << 16) | total_cnt
__device__ int g_pos[MAX_N];
__device__ unsigned g_bitmap[BM_WORDS];
__device__ int g_adj[MAX_N * ADJ_DEG]; // dense present-source pos values
__device__ int g_miss_count;
__device__ int g_miss[MAX_N];

__device__ __forceinline__ uint64_t mix64(uint64_t x) {
    x ^= x >> 33; x *= 0xff51afd7ed558ccdULL;
    x ^= x >> 33; x *= 0xc4ceb9fe1a85ec53ULL;
    x ^= x >> 33;
    return x;
}

__global__ void clear_table_kernel() {
    const int stride = gridDim.x * blockDim.x;
    const int tid = blockIdx.x * blockDim.x + threadIdx.x;
    ulonglong2* h2 = reinterpret_cast<ulonglong2*>(g_hash);
    for (unsigned i = tid; i < TAB_SIZE / 2; i += stride)
        h2[i] = make_ulonglong2(0ULL, 0ULL);
}

__global__ void clear_small_kernel(int N) {
    const int stride = gridDim.x * blockDim.x;
    const int tid = blockIdx.x * blockDim.x + threadIdx.x;
    for (int i = tid; i < N; i += stride) { g_cnt[i] = 0u; g_pos[i] = -1; }
    for (int i = tid; i < BM_WORDS; i += stride) g_bitmap[i] = 0u;
    if (tid == 0) g_miss_count = 0;
}

// Copy present rows, build pos map and presence bitmap.
__global__ void scatter_kernel(const float4* __restrict__ x4,
                               const int* __restrict__ perm,
                               float4* __restrict__ out4,
                               int P, int Cv) {
    const int gtid = blockIdx.x * blockDim.x + threadIdx.x;
    const int r = gtid / Cv;
    const int c = gtid - r * Cv;
    if (r < P) {
        const int node = perm[r];
        if (c == 0) {
            g_pos[node] = r;
            atomicOr(&g_bitmap[node >> 5], 1u << (node & 31));
        }
        out4[(size_t)node * Cv + c] = x4[(size_t)r * Cv + c];
    }
}

// Compact list of missing nodes (pos < 0). Warp-aggregated append.
__global__ void miss_kernel(int N) {
    const int i = blockIdx.x * blockDim.x + threadIdx.x;
    const bool want = (i < N) && (g_pos[i] < 0);
    const unsigned bal = __ballot_sync(0xffffffffu, want);
    if (bal == 0u) return;
    const int lane = threadIdx.x & 31;
    const int leader = __ffs(bal) - 1;
    int base = 0;
    if (lane == leader) base = atomicAdd(&g_miss_count, __popc(bal));
    base = __shfl_sync(0xffffffffu, base, leader);
    if (want) g_miss[base + __popc(bal & ((1u << lane) - 1u))] = i;
}

// UB edges per batch; SMEM bitmap presence; packed-counter adjacency alloc.
__global__ void __launch_bounds__(EDGE_THREADS, 6)
edge_kernel(const int* __restrict__ e0,
            const int* __restrict__ e1,
            int E, int N) {
    __shared__ unsigned s_bm[BM_WORDS];
    const int nw = (N + 31) >> 5;
    for (int i = threadIdx.x; i < nw; i += blockDim.x) s_bm[i] = g_bitmap[i];
    __syncthreads();

    const int tid = blockIdx.x * blockDim.x + threadIdx.x;
    const int TOT = gridDim.x * blockDim.x;
    const int step = TOT * UB;

    for (int base = tid; base < E; base += step) {
        int a[UB], b[UB];
        bool act[UB], ma[UB], mb[UB];

        // Phase 1: coalesced edge loads
        #pragma unroll
        for (int k = 0; k < UB; k++) {
            const int j = base + k * TOT;
            const bool v = (j < E);
            act[k] = v;
            a[k] = v ? e0[j] : 0;
            b[k] = v ? e1[j] : 1;
        }

        // Phase 2: presence checks from SMEM bitmap
        #pragma unroll
        for (int k = 0; k < UB; k++) {
            ma[k] = !((s_bm[a[k] >> 5] >> (a[k] & 31)) & 1u);
            mb[k] = !((s_bm[b[k] >> 5] >> (b[k] & 31)) & 1u);
            act[k] = act[k] && (a[k] != b[k]) && (ma[k] || mb[k]);
        }

        // Phase 3: canonical keys + batched first-probe CAS
        unsigned h[UB];
        unsigned long long old[UB];
        #pragma unroll
        for (int k = 0; k < UB; k++) {
            const int lo = min(a[k], b[k]), hi = max(a[k], b[k]);
            const uint64_t key = (uint64_t)lo * (uint64_t)N + (uint64_t)hi + 1ULL;
            h[k] = (unsigned)mix64(key) & (TAB_SIZE - 1);
            old[k] = act[k] ? atomicCAS(&g_hash[h[k]], 0ULL, key) : 1ULL;
        }

        // Phase 4: resolve rare collisions
        bool win[UB];
        #pragma unroll
        for (int k = 0; k < UB; k++) {
            win[k] = false;
            if (act[k]) {
                const int lo = min(a[k], b[k]), hi = max(a[k], b[k]);
                const uint64_t key = (uint64_t)lo * (uint64_t)N + (uint64_t)hi + 1ULL;
                unsigned long long o = old[k];
                unsigned hh = h[k];
                while (o != 0ULL && o != key) {
                    hh = (hh + 1) & (TAB_SIZE - 1);
                    o = atomicCAS(&g_hash[hh], 0ULL, key);
                }
                win[k] = (o == 0ULL);
            }
        }

        // Phase 5: packed-counter bump; adj store ONLY for present sources.
        #pragma unroll
        for (int k = 0; k < UB; k++) {
            if (win[k]) {
                if (ma[k]) {
                    const bool pres = !mb[k];
                    const unsigned o = atomicAdd(&g_cnt[a[k]],
                                                 pres ? 0x10001u : 1u);
                    if (pres) {
                        const int slot = (int)(o >> 16);
                        if (slot < ADJ_DEG)
                            g_adj[a[k] * ADJ_DEG + slot] = g_pos[b[k]];
                    }
                }
                if (mb[k]) {
                    const bool pres = !ma[k];
                    const unsigned o = atomicAdd(&g_cnt[b[k]],
                                                 pres ? 0x10001u : 1u);
                    if (pres) {
                        const int slot = (int)(o >> 16);
                        if (slot < ADJ_DEG)
                            g_adj[b[k] * ADJ_DEG + slot] = g_pos[a[k]];
                    }
                }
            }
        }
    }
}

// One warp per missing node; dense present-only adjacency; two chains.
__global__ void gather_kernel(const float4* __restrict__ xa4,
                              float4* __restrict__ out4,
                              int M, int Cv) {
    const int lane = threadIdx.x & 31;
    const int li   = lane & 15;
    const int half = lane >> 4;
    const int w = (blockIdx.x * blockDim.x + threadIdx.x) >> 5;
    if (w >= M) return;

    const int t = g_miss[w];
    const unsigned cw = g_cnt[t];
    const int total = (int)(cw & 0xFFFFu);
    const int m     = min((int)(cw >> 16), ADJ_DEG);
    const int4* row = reinterpret_cast<const int4*>(&g_adj[t * ADJ_DEG]);

    float4 acc = make_float4(0.f, 0.f, 0.f, 0.f);
    for (int g = half; g * 4 < m; g += 2) {
        const int4 q = row[g];
        const int bse = g * 4;
        float4 v0 = make_float4(0.f,0.f,0.f,0.f), v1 = v0, v2 = v0, v3 = v0;
        v0 = xa4[(size_t)q.x * Cv + li];
        if (bse + 1 < m) v1 = xa4[(size_t)q.y * Cv + li];
        if (bse + 2 < m) v2 = xa4[(size_t)q.z * Cv + li];
        if (bse + 3 < m) v3 = xa4[(size_t)q.w * Cv + li];
        acc.x += (v0.x + v1.x) + (v2.x + v3.x);
        acc.y += (v0.y + v1.y) + (v2.y + v3.y);
        acc.z += (v0.z + v1.z) + (v2.z + v3.z);
        acc.w += (v0.w + v1.w) + (v2.w + v3.w);
    }

    acc.x += __shfl_xor_sync(0xffffffffu, acc.x, 16);
    acc.y += __shfl_xor_sync(0xffffffffu, acc.y, 16);
    acc.z += __shfl_xor_sync(0xffffffffu, acc.z, 16);
    acc.w += __shfl_xor_sync(0xffffffffu, acc.w, 16);

    if (half == 0) {
        const float inv = (total > 0) ? 1.0f / (float)total : 0.0f;
        acc.x *= inv; acc.y *= inv; acc.z *= inv; acc.w *= inv;
        out4[(size_t)t * Cv + li] = acc;
    }
}

extern "C" void kernel_launch(void* const* d_in, const int* in_sizes, int n_in,
                              void* d_out, int out_size) {
    const float* xa   = (const float*)d_in[0];   // [P, C] f32
    const int*   perm = (const int*)d_in[1];     // [P]
    const int*   ei   = (const int*)d_in[2];     // [2, E]
    (void)n_in;

    const int P  = in_sizes[1];
    const int C  = in_sizes[0] / P;              // 64
    const int Cv = C / 4;                        // 16
    const int E  = in_sizes[2] / 2;
    const int N  = out_size / C;                 // 100000
    const int M  = N - P;
    float* out = (float*)d_out;

    // One-time host resources (no device memory).
    static cudaStream_t s1 = nullptr;
    static cudaEvent_t evFork = nullptr, evSide = nullptr;
    if (s1 == nullptr) {
        cudaStreamCreateWithFlags(&s1, cudaStreamNonBlocking);
        cudaEventCreateWithFlags(&evFork, cudaEventDisableTiming);
        cudaEventCreateWithFlags(&evSide, cudaEventDisableTiming);
    }

    // Fork: side chain (clear_small -> scatter -> miss) || main clear_table.
    // Joined BEFORE edge: nothing ever co-runs with the edge kernel.
    cudaEventRecord(evFork, 0);
    cudaStreamWaitEvent(s1, evFork, 0);

    clear_small_kernel<<<256, 256, 0, s1>>>(N);
    {
        const int work = P * Cv;
        scatter_kernel<<<(work + 255) / 256, 256, 0, s1>>>(
            (const float4*)xa, perm, (float4*)out, P, Cv);
    }
    miss_kernel<<<(N + 255) / 256, 256, 0, s1>>>(N);
    cudaEventRecord(evSide, s1);

    clear_table_kernel<<<2048, 256>>>();

    cudaStreamWaitEvent(0, evSide, 0);
    edge_kernel<<<EDGE_BLOCKS, EDGE_THREADS>>>(ei, ei + E, E, N);

    {
        const long long work = (long long)M * 32;
        const int blocks = (int)((work + 255) / 256);
        gather_kernel<<<blocks, 256>>>((const float4*)xa, (float4*)out, M, Cv);
    }
}